// round 16
// baseline (speedup 1.0000x reference)
#include <cuda_runtime.h>
#include <cuda_bf16.h>
#include <math.h>
#include <stdint.h>

#define B 4
#define S 2048
#define E 1024
#define H 16
#define HD 64
#define EPS 1.1920928955078125e-07f

#define BMA 128      // q rows per CTA (attn)
#define BNA 64       // kv cols per tile
#define LDT 72       // attn smem row stride (bf16 elems) = 144B, conflict-free
#define LDP 40       // proj smem row stride (bf16 elems) = 80B, conflict-free
#define SMEM_ATTN 73728
#define SMEM_PROJ 51200   // (256*LDP*2 + 64*LDP*2) elems * 2B

// ---------------- scratch (__device__ globals; no allocs allowed) -----------
__device__ __nv_bfloat16 g_Qh[B*H*S*HD], g_Ql[B*H*S*HD];
__device__ __nv_bfloat16 g_Kh[B*H*S*HD], g_Kl[B*H*S*HD];
__device__ __nv_bfloat16 g_Vh[B*H*S*HD], g_Vl[B*H*S*HD];
__device__ __nv_bfloat16 g_Ch[B*S*E],   g_Cl[B*S*E];
__device__ __nv_bfloat16 g_Wh[E*E],     g_Wl[E*E];

// ---------------- helpers ---------------------------------------------------
__device__ __forceinline__ void mma16816(float d[4], const uint32_t a[4], const uint32_t b[2]) {
    asm volatile(
        "mma.sync.aligned.m16n8k16.row.col.f32.bf16.bf16.f32 "
        "{%0,%1,%2,%3},{%4,%5,%6,%7},{%8,%9},{%0,%1,%2,%3};"
        : "+f"(d[0]), "+f"(d[1]), "+f"(d[2]), "+f"(d[3])
        : "r"(a[0]), "r"(a[1]), "r"(a[2]), "r"(a[3]), "r"(b[0]), "r"(b[1]));
}
__device__ __forceinline__ uint32_t packb(__nv_bfloat16 x, __nv_bfloat16 y) {
    __nv_bfloat162 t = __halves2bfloat162(x, y);
    return *reinterpret_cast<uint32_t*>(&t);
}
__device__ __forceinline__ uint32_t lds32(const __nv_bfloat16* p) {
    return *reinterpret_cast<const uint32_t*>(p);
}
// pack two floats to bf16x2 (lo=x, hi=y) with RN — same bits as packb of
// __float2bfloat16_rn pair, one instruction.
__device__ __forceinline__ uint32_t cvtpack(float x, float y) {
    uint32_t r;
    asm("cvt.rn.bf16x2.f32 %0, %1, %2;" : "=r"(r) : "f"(y), "f"(x));
    return r;
}
__device__ __forceinline__ void split2(float x, float y, uint32_t& hi, uint32_t& lo) {
    __nv_bfloat16 h0 = __float2bfloat16_rn(x), h1 = __float2bfloat16_rn(y);
    hi = packb(h0, h1);
    lo = packb(__float2bfloat16_rn(x - __bfloat162float(h0)),
               __float2bfloat16_rn(y - __bfloat162float(h1)));
}

// ---------------- kernel 1: fused rmsnorm + rope + bf16 hi/lo split ---------
__global__ __launch_bounds__(256) void prep_kernel(
    const float* __restrict__ q, const float* __restrict__ k,
    const float* __restrict__ v,
    const float* __restrict__ qw, const float* __restrict__ kw)
{
    int warp = (blockIdx.x * blockDim.x + threadIdx.x) >> 5;
    int lane = threadIdx.x & 31;
    int h  = warp & (H - 1);
    int bs = warp >> 4;            // b*S + s
    int s  = bs & (S - 1);
    int b  = bs >> 11;             // /2048

    int gi = bs * E + h * HD + 2 * lane;
    float2 qv = *reinterpret_cast<const float2*>(q + gi);
    float2 kv = *reinterpret_cast<const float2*>(k + gi);
    float2 vv = *reinterpret_cast<const float2*>(v + gi);

    float inv_f = exp2f(-(float)lane * 0.41524101186092029f);
    float ang = (float)s * inv_f;
    float cs = cosf(ang), sn = sinf(ang);

    float w1q = qw[2 * lane], w2q = qw[2 * lane + 1];
    float w1k = kw[2 * lane], w2k = kw[2 * lane + 1];

    float ssq = qv.x * qv.x + qv.y * qv.y;
    float ssk = kv.x * kv.x + kv.y * kv.y;
    #pragma unroll
    for (int off = 16; off; off >>= 1) {
        ssq += __shfl_xor_sync(0xffffffff, ssq, off);
        ssk += __shfl_xor_sync(0xffffffff, ssk, off);
    }
    float rq = rsqrtf(ssq * (1.0f / HD) + EPS);
    float rk = rsqrtf(ssk * (1.0f / HD) + EPS);

    float qx1 = qv.x * rq * w1q, qx2 = qv.y * rq * w2q;
    float kx1 = kv.x * rk * w1k, kx2 = kv.y * rk * w2k;

    float qox = qx1 * cs - qx2 * sn, qoy = qx1 * sn + qx2 * cs;
    float kox = kx1 * cs - kx2 * sn, koy = kx1 * sn + kx2 * cs;

    const float sc = 0.125f * 1.4426950408889634f; // HD^-0.5 * log2(e)
    qox *= sc; qoy *= sc;

    int u = (((b * H + h) * S + s) * HD + 2 * lane) >> 1;
    uint32_t hi, lo;
    split2(qox, qoy, hi, lo);
    reinterpret_cast<uint32_t*>(g_Qh)[u] = hi;
    reinterpret_cast<uint32_t*>(g_Ql)[u] = lo;
    split2(kox, koy, hi, lo);
    reinterpret_cast<uint32_t*>(g_Kh)[u] = hi;
    reinterpret_cast<uint32_t*>(g_Kl)[u] = lo;
    split2(vv.x, vv.y, hi, lo);
    reinterpret_cast<uint32_t*>(g_Vh)[u] = hi;
    reinterpret_cast<uint32_t*>(g_Vl)[u] = lo;
}

// ---------------- kernel 2: W -> bf16 hi/lo ---------------------------------
__global__ void wconv_kernel(const float* __restrict__ W) {
    int i = blockIdx.x * 256 + threadIdx.x;
    float x = W[i];
    __nv_bfloat16 hi = __float2bfloat16_rn(x);
    g_Wh[i] = hi;
    g_Wl[i] = __float2bfloat16_rn(x - __bfloat162float(hi));
}

// ---------------- kernel 3: flash attention (4 warps, 2 row-blocks/warp) ----
// 128 threads = 4 warps; warp w owns rows [16w,16w+16) and [64+16w,64+16w+16)
// of the 128-row q tile. K/V B-fragments are shared by both row-blocks.
__global__ __launch_bounds__(128, 2) void attn_kernel()
{
    extern __shared__ __nv_bfloat16 smb[];
    __nv_bfloat16* sQh  = smb;              // [128][LDT]
    __nv_bfloat16* sQl  = smb + 9216;
    __nv_bfloat16* sKh  = smb + 18432;      // [64][LDT]  (row kv, col d)
    __nv_bfloat16* sKl  = smb + 23040;
    __nv_bfloat16* sVth = smb + 27648;      // [64][LDT]  V transposed (row d, col kv)
    __nv_bfloat16* sVtl = smb + 32256;

    int bh = blockIdx.y, qt = blockIdx.x;
    int tid = threadIdx.x, w = tid >> 5, t = tid & 31;
    int gid = t >> 2, tig = t & 3;
    int w16 = w * 16;

    size_t base = (size_t)bh * S * HD;
    const __nv_bfloat16* Qhb = g_Qh + base + (size_t)qt * BMA * HD;
    const __nv_bfloat16* Qlb = g_Ql + base + (size_t)qt * BMA * HD;
    const __nv_bfloat16* Khb = g_Kh + base;
    const __nv_bfloat16* Klb = g_Kl + base;
    const __nv_bfloat16* Vhb = g_Vh + base;
    const __nv_bfloat16* Vlb = g_Vl + base;

    #pragma unroll
    for (int i = 0; i < 8; i++) {
        int lin = i * 128 + tid;
        int r = lin >> 3, c = lin & 7;
        *reinterpret_cast<uint4*>(sQh + r * LDT + c * 8) =
            *reinterpret_cast<const uint4*>(Qhb + r * HD + c * 8);
        *reinterpret_cast<uint4*>(sQl + r * LDT + c * 8) =
            *reinterpret_cast<const uint4*>(Qlb + r * HD + c * 8);
    }
    __syncthreads();

    // Q-hi fragments for both row-blocks cached in registers.
    uint32_t qfh0[4][4], qfh1[4][4];
    #pragma unroll
    for (int kk = 0; kk < 4; kk++) {
        int kb = kk * 16 + 2 * tig;
        const __nv_bfloat16* q0h = sQh + (w16 + gid) * LDT + kb;
        const __nv_bfloat16* q1h = sQh + (64 + w16 + gid) * LDT + kb;
        qfh0[kk][0] = lds32(q0h);
        qfh0[kk][1] = lds32(q0h + 8 * LDT);
        qfh0[kk][2] = lds32(q0h + 8);
        qfh0[kk][3] = lds32(q0h + 8 * LDT + 8);
        qfh1[kk][0] = lds32(q1h);
        qfh1[kk][1] = lds32(q1h + 8 * LDT);
        qfh1[kk][2] = lds32(q1h + 8);
        qfh1[kk][3] = lds32(q1h + 8 * LDT + 8);
    }

    float accO0[8][4], accO1[8][4];
    #pragma unroll
    for (int j = 0; j < 8; j++)
        #pragma unroll
        for (int c = 0; c < 4; c++) { accO0[j][c] = 0.f; accO1[j][c] = 0.f; }
    float l0 = 0.f, l1 = 0.f, l2 = 0.f, l3 = 0.f;

    for (int kt = 0; kt < S / BNA; kt++) {
        __syncthreads();
        #pragma unroll
        for (int i = 0; i < 4; i++) {
            int lin = i * 128 + tid;
            int r = lin >> 3, c = lin & 7;
            size_t g = (size_t)(kt * BNA + r) * HD + c * 8;
            *reinterpret_cast<uint4*>(sKh + r * LDT + c * 8) =
                *reinterpret_cast<const uint4*>(Khb + g);
            *reinterpret_cast<uint4*>(sKl + r * LDT + c * 8) =
                *reinterpret_cast<const uint4*>(Klb + g);
            uint4 vh = *reinterpret_cast<const uint4*>(Vhb + g);
            uint4 vl = *reinterpret_cast<const uint4*>(Vlb + g);
            const __nv_bfloat16* ph = reinterpret_cast<const __nv_bfloat16*>(&vh);
            const __nv_bfloat16* pl = reinterpret_cast<const __nv_bfloat16*>(&vl);
            #pragma unroll
            for (int jj = 0; jj < 8; jj++) {
                sVth[(c * 8 + jj) * LDT + r] = ph[jj];
                sVtl[(c * 8 + jj) * LDT + r] = pl[jj];
            }
        }
        __syncthreads();

        // ---- S = Q K^T (bf16x3), both row-blocks share K fragments ----
        float accS0[8][4], accS1[8][4];
        #pragma unroll
        for (int j = 0; j < 8; j++)
            #pragma unroll
            for (int c = 0; c < 4; c++) { accS0[j][c] = 0.f; accS1[j][c] = 0.f; }

        #pragma unroll
        for (int kk = 0; kk < 4; kk++) {
            int kb = kk * 16 + 2 * tig;
            const __nv_bfloat16* q0l = sQl + (w16 + gid) * LDT + kb;
            const __nv_bfloat16* q1l = sQl + (64 + w16 + gid) * LDT + kb;
            uint32_t al0[4], al1[4];
            al0[0] = lds32(q0l);
            al0[1] = lds32(q0l + 8 * LDT);
            al0[2] = lds32(q0l + 8);
            al0[3] = lds32(q0l + 8 * LDT + 8);
            al1[0] = lds32(q1l);
            al1[1] = lds32(q1l + 8 * LDT);
            al1[2] = lds32(q1l + 8);
            al1[3] = lds32(q1l + 8 * LDT + 8);
            #pragma unroll
            for (int j = 0; j < 8; j++) {
                const __nv_bfloat16* kr_h = sKh + (j * 8 + gid) * LDT + kb;
                const __nv_bfloat16* kr_l = sKl + (j * 8 + gid) * LDT + kb;
                uint32_t bhf[2] = { lds32(kr_h), lds32(kr_h + 8) };
                uint32_t blf[2] = { lds32(kr_l), lds32(kr_l + 8) };
                mma16816(accS0[j], qfh0[kk], bhf);
                mma16816(accS0[j], qfh0[kk], blf);
                mma16816(accS0[j], al0, bhf);
                mma16816(accS1[j], qfh1[kk], bhf);
                mma16816(accS1[j], qfh1[kk], blf);
                mma16816(accS1[j], al1, bhf);
            }
        }

        // ---- softmax numerator: p = exp2(score), fixed max = 0 -------------
        // |score*log2e| <= 11.54 (rmsnorm bounds |q|,|k| = 8): no overflow.
        #pragma unroll
        for (int j = 0; j < 8; j++) {
            accS0[j][0] = exp2f(accS0[j][0]);
            accS0[j][1] = exp2f(accS0[j][1]);
            accS0[j][2] = exp2f(accS0[j][2]);
            accS0[j][3] = exp2f(accS0[j][3]);
            l0 += accS0[j][0] + accS0[j][1];
            l1 += accS0[j][2] + accS0[j][3];
            accS1[j][0] = exp2f(accS1[j][0]);
            accS1[j][1] = exp2f(accS1[j][1]);
            accS1[j][2] = exp2f(accS1[j][2]);
            accS1[j][3] = exp2f(accS1[j][3]);
            l2 += accS1[j][0] + accS1[j][1];
            l3 += accS1[j][2] + accS1[j][3];
        }

        // ---- O += P V (bf16x3, P in regs; V fragments shared) ----
        #pragma unroll
        for (int kk = 0; kk < 4; kk++) {
            uint32_t pah0[4], pal0[4], pah1[4], pal1[4];
            #pragma unroll
            for (int hseg = 0; hseg < 4; hseg++) {
                const float* ps0 = (hseg < 2) ? accS0[2 * kk] : accS0[2 * kk + 1];
                const float* ps1 = (hseg < 2) ? accS1[2 * kk] : accS1[2 * kk + 1];
                float x0 = ps0[(hseg & 1) * 2], y0 = ps0[(hseg & 1) * 2 + 1];
                float x1 = ps1[(hseg & 1) * 2], y1 = ps1[(hseg & 1) * 2 + 1];
                uint32_t hw0 = cvtpack(x0, y0);
                uint32_t hw1 = cvtpack(x1, y1);
                pah0[hseg] = hw0;
                pah1[hseg] = hw1;
                pal0[hseg] = cvtpack(x0 - __uint_as_float(hw0 << 16),
                                     y0 - __uint_as_float(hw0 & 0xffff0000u));
                pal1[hseg] = cvtpack(x1 - __uint_as_float(hw1 << 16),
                                     y1 - __uint_as_float(hw1 & 0xffff0000u));
            }
            int kvb = kk * 16 + 2 * tig;
            #pragma unroll
            for (int j = 0; j < 8; j++) {
                const __nv_bfloat16* vr_h = sVth + (j * 8 + gid) * LDT + kvb;
                const __nv_bfloat16* vr_l = sVtl + (j * 8 + gid) * LDT + kvb;
                uint32_t vbh[2] = { lds32(vr_h), lds32(vr_h + 8) };
                uint32_t vbl[2] = { lds32(vr_l), lds32(vr_l + 8) };
                mma16816(accO0[j], pah0, vbh);
                mma16816(accO0[j], pah0, vbl);
                mma16816(accO0[j], pal0, vbh);
                mma16816(accO1[j], pah1, vbh);
                mma16816(accO1[j], pah1, vbl);
                mma16816(accO1[j], pal1, vbh);
            }
        }
    }

    // ---- epilogue: quad reduction of l, normalize, bf16 hi/lo ctx ----
    #pragma unroll
    for (int off = 1; off <= 2; off <<= 1) {
        l0 += __shfl_xor_sync(0xffffffff, l0, off);
        l1 += __shfl_xor_sync(0xffffffff, l1, off);
        l2 += __shfl_xor_sync(0xffffffff, l2, off);
        l3 += __shfl_xor_sync(0xffffffff, l3, off);
    }
    int b = bh >> 4, h = bh & 15;
    float i0 = 1.0f / l0, i1 = 1.0f / l1;
    float i2 = 1.0f / l2, i3 = 1.0f / l3;
    int rowA = b * S + qt * BMA + w16 + gid;        // block0
    int rowC = rowA + 64;                            // block1
    #pragma unroll
    for (int j = 0; j < 8; j++) {
        int col = h * HD + j * 8 + 2 * tig;
        float x0 = accO0[j][0] * i0, x1 = accO0[j][1] * i0;
        float x2 = accO0[j][2] * i1, x3 = accO0[j][3] * i1;
        float x4 = accO1[j][0] * i2, x5 = accO1[j][1] * i2;
        float x6 = accO1[j][2] * i3, x7 = accO1[j][3] * i3;
        uint32_t hi, lo;
        size_t u;
        split2(x0, x1, hi, lo);
        u = ((size_t)rowA * E + col) >> 1;
        reinterpret_cast<uint32_t*>(g_Ch)[u] = hi;
        reinterpret_cast<uint32_t*>(g_Cl)[u] = lo;
        split2(x2, x3, hi, lo);
        u = ((size_t)(rowA + 8) * E + col) >> 1;
        reinterpret_cast<uint32_t*>(g_Ch)[u] = hi;
        reinterpret_cast<uint32_t*>(g_Cl)[u] = lo;
        split2(x4, x5, hi, lo);
        u = ((size_t)rowC * E + col) >> 1;
        reinterpret_cast<uint32_t*>(g_Ch)[u] = hi;
        reinterpret_cast<uint32_t*>(g_Cl)[u] = lo;
        split2(x6, x7, hi, lo);
        u = ((size_t)(rowC + 8) * E + col) >> 1;
        reinterpret_cast<uint32_t*>(g_Ch)[u] = hi;
        reinterpret_cast<uint32_t*>(g_Cl)[u] = lo;
    }
}

// ---------------- kernel 4: projection (bf16x3 mma, M=256: 2 blocks/warp) ---
__global__ __launch_bounds__(256) void proj_kernel(
    const float* __restrict__ bias, float* __restrict__ out)
{
    extern __shared__ __nv_bfloat16 smp[];
    __nv_bfloat16* sAh = smp;                   // [256][LDP]
    __nv_bfloat16* sAl = smp + 256 * LDP;
    __nv_bfloat16* sBh = smp + 512 * LDP;       // [64][LDP]
    __nv_bfloat16* sBl = smp + 512 * LDP + 64 * LDP;

    int tid = threadIdx.x, w = tid >> 5, t = tid & 31;
    int gid = t >> 2, tig = t & 3;
    int w16 = w * 16;
    int nb = blockIdx.x * 64, mb = blockIdx.y * 256;

    float acc0[8][4], acc1[8][4];
    #pragma unroll
    for (int j = 0; j < 8; j++)
        #pragma unroll
        for (int c = 0; c < 4; c++) { acc0[j][c] = 0.f; acc1[j][c] = 0.f; }

    for (int kt = 0; kt < E / 32; kt++) {
        __syncthreads();
        #pragma unroll
        for (int i = 0; i < 4; i++) {
            int lin = i * 256 + tid;
            int r = lin >> 2, c = lin & 3;
            size_t g = (size_t)(mb + r) * E + kt * 32 + c * 8;
            *reinterpret_cast<uint4*>(sAh + r * LDP + c * 8) =
                *reinterpret_cast<const uint4*>(g_Ch + g);
            *reinterpret_cast<uint4*>(sAl + r * LDP + c * 8) =
                *reinterpret_cast<const uint4*>(g_Cl + g);
        }
        {
            int r = tid >> 2, c = tid & 3;
            size_t g = (size_t)(nb + r) * E + kt * 32 + c * 8;
            *reinterpret_cast<uint4*>(sBh + r * LDP + c * 8) =
                *reinterpret_cast<const uint4*>(g_Wh + g);
            *reinterpret_cast<uint4*>(sBl + r * LDP + c * 8) =
                *reinterpret_cast<const uint4*>(g_Wl + g);
        }
        __syncthreads();

        #pragma unroll
        for (int kk = 0; kk < 2; kk++) {
            int kb = kk * 16 + 2 * tig;
            const __nv_bfloat16* a0h = sAh + (w16 + gid) * LDP + kb;
            const __nv_bfloat16* a0l = sAl + (w16 + gid) * LDP + kb;
            const __nv_bfloat16* a1h = sAh + (128 + w16 + gid) * LDP + kb;
            const __nv_bfloat16* a1l = sAl + (128 + w16 + gid) * LDP + kb;
            uint32_t ah0[4], al0[4], ah1[4], al1[4];
            ah0[0] = lds32(a0h);               al0[0] = lds32(a0l);
            ah0[1] = lds32(a0h + 8 * LDP);     al0[1] = lds32(a0l + 8 * LDP);
            ah0[2] = lds32(a0h + 8);           al0[2] = lds32(a0l + 8);
            ah0[3] = lds32(a0h + 8 * LDP + 8); al0[3] = lds32(a0l + 8 * LDP + 8);
            ah1[0] = lds32(a1h);               al1[0] = lds32(a1l);
            ah1[1] = lds32(a1h + 8 * LDP);     al1[1] = lds32(a1l + 8 * LDP);
            ah1[2] = lds32(a1h + 8);           al1[2] = lds32(a1l + 8);
            ah1[3] = lds32(a1h + 8 * LDP + 8); al1[3] = lds32(a1l + 8 * LDP + 8);
            #pragma unroll
            for (int j = 0; j < 8; j++) {
                const __nv_bfloat16* br_h = sBh + (j * 8 + gid) * LDP + kb;
                const __nv_bfloat16* br_l = sBl + (j * 8 + gid) * LDP + kb;
                uint32_t bhf[2] = { lds32(br_h), lds32(br_h + 8) };
                uint32_t blf[2] = { lds32(br_l), lds32(br_l + 8) };
                mma16816(acc0[j], ah0, bhf);
                mma16816(acc0[j], ah0, blf);
                mma16816(acc0[j], al0, bhf);
                mma16816(acc1[j], ah1, bhf);
                mma16816(acc1[j], ah1, blf);
                mma16816(acc1[j], al1, bhf);
            }
        }
    }

    int r0 = mb + w16 + gid;
    #pragma unroll
    for (int j = 0; j < 8; j++) {
        int c = nb + j * 8 + 2 * tig;
        float b0 = bias[c], b1 = bias[c + 1];
        *reinterpret_cast<float2*>(out + (size_t)r0 * E + c) =
            make_float2(acc0[j][0] + b0, acc0[j][1] + b1);
        *reinterpret_cast<float2*>(out + (size_t)(r0 + 8) * E + c) =
            make_float2(acc0[j][2] + b0, acc0[j][3] + b1);
        *reinterpret_cast<float2*>(out + (size_t)(r0 + 128) * E + c) =
            make_float2(acc1[j][0] + b0, acc1[j][1] + b1);
        *reinterpret_cast<float2*>(out + (size_t)(r0 + 136) * E + c) =
            make_float2(acc1[j][2] + b0, acc1[j][3] + b1);
    }
}

// ---------------------------------------------------------------------------
extern "C" void kernel_launch(void* const* d_in, const int* in_sizes, int n_in,
                              void* d_out, int out_size)
{
    const float* q    = (const float*)d_in[0];
    const float* k    = (const float*)d_in[1];
    const float* v    = (const float*)d_in[2];
    const float* qw   = (const float*)d_in[3];
    const float* kw   = (const float*)d_in[4];
    const float* W    = (const float*)d_in[5];
    const float* bias = (const float*)d_in[6];
    float* out = (float*)d_out;

    cudaFuncSetAttribute(attn_kernel,
                         cudaFuncAttributeMaxDynamicSharedMemorySize, SMEM_ATTN);
    cudaFuncSetAttribute(proj_kernel,
                         cudaFuncAttributeMaxDynamicSharedMemorySize, SMEM_PROJ);

    prep_kernel<<<(B * S * H) / 8, 256>>>(q, k, v, qw, kw);
    wconv_kernel<<<(E * E) / 256, 256>>>(W);
    attn_kernel<<<dim3(S / BMA, B * H), 128, SMEM_ATTN>>>();
    proj_kernel<<<dim3(E / 64, (B * S) / 256), 256, SMEM_PROJ>>>(bias, out);
}

// round 17
// speedup vs baseline: 1.0386x; 1.0386x over previous
#include <cuda_runtime.h>
#include <cuda_bf16.h>
#include <math.h>
#include <stdint.h>

#define B 4
#define S 2048
#define E 1024
#define H 16
#define HD 64
#define EPS 1.1920928955078125e-07f

#define BMA 128      // q rows per CTA (attn)
#define BNA 64       // kv cols per tile
#define LDT 72       // attn smem row stride (bf16 elems) = 144B, conflict-free
#define LDP 40       // proj smem row stride (bf16 elems) = 80B, conflict-free
#define SMEM_ATTN 73728
#define PROJ_STAGE_ELEMS (640 * LDP)          // (A 512*LDP + B 128*LDP) elems
#define SMEM_PROJ (2 * PROJ_STAGE_ELEMS * 2)  // 2 stages, bytes = 102400

// ---------------- scratch (__device__ globals; no allocs allowed) -----------
__device__ __nv_bfloat16 g_Qh[B*H*S*HD], g_Ql[B*H*S*HD];
__device__ __nv_bfloat16 g_Kh[B*H*S*HD], g_Kl[B*H*S*HD];
__device__ __nv_bfloat16 g_Vh[B*H*S*HD], g_Vl[B*H*S*HD];
__device__ __nv_bfloat16 g_Ch[B*S*E],   g_Cl[B*S*E];
__device__ __nv_bfloat16 g_Wh[E*E],     g_Wl[E*E];

// ---------------- helpers ---------------------------------------------------
__device__ __forceinline__ void mma16816(float d[4], const uint32_t a[4], const uint32_t b[2]) {
    asm volatile(
        "mma.sync.aligned.m16n8k16.row.col.f32.bf16.bf16.f32 "
        "{%0,%1,%2,%3},{%4,%5,%6,%7},{%8,%9},{%0,%1,%2,%3};"
        : "+f"(d[0]), "+f"(d[1]), "+f"(d[2]), "+f"(d[3])
        : "r"(a[0]), "r"(a[1]), "r"(a[2]), "r"(a[3]), "r"(b[0]), "r"(b[1]));
}
__device__ __forceinline__ uint32_t packb(__nv_bfloat16 x, __nv_bfloat16 y) {
    __nv_bfloat162 t = __halves2bfloat162(x, y);
    return *reinterpret_cast<uint32_t*>(&t);
}
__device__ __forceinline__ uint32_t lds32(const __nv_bfloat16* p) {
    return *reinterpret_cast<const uint32_t*>(p);
}
__device__ __forceinline__ uint32_t cvtpack(float x, float y) {
    uint32_t r;
    asm("cvt.rn.bf16x2.f32 %0, %1, %2;" : "=r"(r) : "f"(y), "f"(x));
    return r;
}
__device__ __forceinline__ void split2(float x, float y, uint32_t& hi, uint32_t& lo) {
    __nv_bfloat16 h0 = __float2bfloat16_rn(x), h1 = __float2bfloat16_rn(y);
    hi = packb(h0, h1);
    lo = packb(__float2bfloat16_rn(x - __bfloat162float(h0)),
               __float2bfloat16_rn(y - __bfloat162float(h1)));
}
__device__ __forceinline__ void cpasync16(__nv_bfloat16* smem, const __nv_bfloat16* gmem) {
    uint32_t s = (uint32_t)__cvta_generic_to_shared(smem);
    asm volatile("cp.async.cg.shared.global [%0], [%1], 16;" :: "r"(s), "l"(gmem));
}
#define CP_COMMIT() asm volatile("cp.async.commit_group;" ::: "memory")
#define CP_WAIT0()  asm volatile("cp.async.wait_group 0;" ::: "memory")

// ---------------- kernel 1: fused rmsnorm + rope + bf16 hi/lo split ---------
__global__ __launch_bounds__(256) void prep_kernel(
    const float* __restrict__ q, const float* __restrict__ k,
    const float* __restrict__ v,
    const float* __restrict__ qw, const float* __restrict__ kw)
{
    int warp = (blockIdx.x * blockDim.x + threadIdx.x) >> 5;
    int lane = threadIdx.x & 31;
    int h  = warp & (H - 1);
    int bs = warp >> 4;            // b*S + s
    int s  = bs & (S - 1);
    int b  = bs >> 11;             // /2048

    int gi = bs * E + h * HD + 2 * lane;
    float2 qv = *reinterpret_cast<const float2*>(q + gi);
    float2 kv = *reinterpret_cast<const float2*>(k + gi);
    float2 vv = *reinterpret_cast<const float2*>(v + gi);

    float inv_f = exp2f(-(float)lane * 0.41524101186092029f);
    float ang = (float)s * inv_f;
    float cs = cosf(ang), sn = sinf(ang);

    float w1q = qw[2 * lane], w2q = qw[2 * lane + 1];
    float w1k = kw[2 * lane], w2k = kw[2 * lane + 1];

    float ssq = qv.x * qv.x + qv.y * qv.y;
    float ssk = kv.x * kv.x + kv.y * kv.y;
    #pragma unroll
    for (int off = 16; off; off >>= 1) {
        ssq += __shfl_xor_sync(0xffffffff, ssq, off);
        ssk += __shfl_xor_sync(0xffffffff, ssk, off);
    }
    float rq = rsqrtf(ssq * (1.0f / HD) + EPS);
    float rk = rsqrtf(ssk * (1.0f / HD) + EPS);

    float qx1 = qv.x * rq * w1q, qx2 = qv.y * rq * w2q;
    float kx1 = kv.x * rk * w1k, kx2 = kv.y * rk * w2k;

    float qox = qx1 * cs - qx2 * sn, qoy = qx1 * sn + qx2 * cs;
    float kox = kx1 * cs - kx2 * sn, koy = kx1 * sn + kx2 * cs;

    const float sc = 0.125f * 1.4426950408889634f; // HD^-0.5 * log2(e)
    qox *= sc; qoy *= sc;

    int u = (((b * H + h) * S + s) * HD + 2 * lane) >> 1;
    uint32_t hi, lo;
    split2(qox, qoy, hi, lo);
    reinterpret_cast<uint32_t*>(g_Qh)[u] = hi;
    reinterpret_cast<uint32_t*>(g_Ql)[u] = lo;
    split2(kox, koy, hi, lo);
    reinterpret_cast<uint32_t*>(g_Kh)[u] = hi;
    reinterpret_cast<uint32_t*>(g_Kl)[u] = lo;
    split2(vv.x, vv.y, hi, lo);
    reinterpret_cast<uint32_t*>(g_Vh)[u] = hi;
    reinterpret_cast<uint32_t*>(g_Vl)[u] = lo;
}

// ---------------- kernel 2: W -> bf16 hi/lo ---------------------------------
__global__ void wconv_kernel(const float* __restrict__ W) {
    int i = blockIdx.x * 256 + threadIdx.x;
    float x = W[i];
    __nv_bfloat16 hi = __float2bfloat16_rn(x);
    g_Wh[i] = hi;
    g_Wl[i] = __float2bfloat16_rn(x - __bfloat162float(hi));
}

// ---------------- kernel 3: flash attention (R15-proven body, unchanged) ----
// 256 threads = 8 warps; warp w owns rows [16w,16w+16) of a 128-row q tile.
__global__ __launch_bounds__(256, 2) void attn_kernel()
{
    extern __shared__ __nv_bfloat16 smb[];
    __nv_bfloat16* sQh  = smb;              // [128][LDT]
    __nv_bfloat16* sQl  = smb + 9216;
    __nv_bfloat16* sKh  = smb + 18432;      // [64][LDT]  (row kv, col d)
    __nv_bfloat16* sKl  = smb + 23040;
    __nv_bfloat16* sVth = smb + 27648;      // [64][LDT]  V transposed (row d, col kv)
    __nv_bfloat16* sVtl = smb + 32256;

    int bh = blockIdx.y, qt = blockIdx.x;
    int tid = threadIdx.x, w = tid >> 5, t = tid & 31;
    int gid = t >> 2, tig = t & 3;
    int w16 = w * 16;

    size_t base = (size_t)bh * S * HD;
    const __nv_bfloat16* Qhb = g_Qh + base + (size_t)qt * BMA * HD;
    const __nv_bfloat16* Qlb = g_Ql + base + (size_t)qt * BMA * HD;
    const __nv_bfloat16* Khb = g_Kh + base;
    const __nv_bfloat16* Klb = g_Kl + base;
    const __nv_bfloat16* Vhb = g_Vh + base;
    const __nv_bfloat16* Vlb = g_Vl + base;

    #pragma unroll
    for (int i = 0; i < 4; i++) {
        int lin = i * 256 + tid;
        int r = lin >> 3, c = lin & 7;
        *reinterpret_cast<uint4*>(sQh + r * LDT + c * 8) =
            *reinterpret_cast<const uint4*>(Qhb + r * HD + c * 8);
        *reinterpret_cast<uint4*>(sQl + r * LDT + c * 8) =
            *reinterpret_cast<const uint4*>(Qlb + r * HD + c * 8);
    }
    __syncthreads();

    // Q-hi fragments cached in registers for the whole kv loop (Q constant).
    uint32_t qfh[4][4];
    #pragma unroll
    for (int kk = 0; kk < 4; kk++) {
        int kb = kk * 16 + 2 * tig;
        const __nv_bfloat16* q0h = sQh + (w16 + gid) * LDT + kb;
        qfh[kk][0] = lds32(q0h);
        qfh[kk][1] = lds32(q0h + 8 * LDT);
        qfh[kk][2] = lds32(q0h + 8);
        qfh[kk][3] = lds32(q0h + 8 * LDT + 8);
    }

    float accO[8][4];
    #pragma unroll
    for (int j = 0; j < 8; j++)
        #pragma unroll
        for (int c = 0; c < 4; c++) accO[j][c] = 0.f;
    float l0 = 0.f, l1 = 0.f;

    for (int kt = 0; kt < S / BNA; kt++) {
        __syncthreads();
        #pragma unroll
        for (int i = 0; i < 2; i++) {
            int lin = i * 256 + tid;
            int r = lin >> 3, c = lin & 7;
            size_t g = (size_t)(kt * BNA + r) * HD + c * 8;
            *reinterpret_cast<uint4*>(sKh + r * LDT + c * 8) =
                *reinterpret_cast<const uint4*>(Khb + g);
            *reinterpret_cast<uint4*>(sKl + r * LDT + c * 8) =
                *reinterpret_cast<const uint4*>(Klb + g);
            uint4 vh = *reinterpret_cast<const uint4*>(Vhb + g);
            uint4 vl = *reinterpret_cast<const uint4*>(Vlb + g);
            const __nv_bfloat16* ph = reinterpret_cast<const __nv_bfloat16*>(&vh);
            const __nv_bfloat16* pl = reinterpret_cast<const __nv_bfloat16*>(&vl);
            #pragma unroll
            for (int jj = 0; jj < 8; jj++) {
                sVth[(c * 8 + jj) * LDT + r] = ph[jj];
                sVtl[(c * 8 + jj) * LDT + r] = pl[jj];
            }
        }
        __syncthreads();

        // ---- S = Q K^T (bf16x3) ----
        float accS[8][4];
        #pragma unroll
        for (int j = 0; j < 8; j++)
            #pragma unroll
            for (int c = 0; c < 4; c++) accS[j][c] = 0.f;

        #pragma unroll
        for (int kk = 0; kk < 4; kk++) {
            int kb = kk * 16 + 2 * tig;
            const __nv_bfloat16* q0l = sQl + (w16 + gid) * LDT + kb;
            uint32_t al[4];
            al[0] = lds32(q0l);
            al[1] = lds32(q0l + 8 * LDT);
            al[2] = lds32(q0l + 8);
            al[3] = lds32(q0l + 8 * LDT + 8);
            #pragma unroll
            for (int j = 0; j < 8; j++) {
                const __nv_bfloat16* kr_h = sKh + (j * 8 + gid) * LDT + kb;
                const __nv_bfloat16* kr_l = sKl + (j * 8 + gid) * LDT + kb;
                uint32_t bhf[2] = { lds32(kr_h), lds32(kr_h + 8) };
                uint32_t blf[2] = { lds32(kr_l), lds32(kr_l + 8) };
                mma16816(accS[j], qfh[kk], bhf);
                mma16816(accS[j], qfh[kk], blf);
                mma16816(accS[j], al, bhf);
            }
        }

        // ---- softmax numerator: p = exp2(score), fixed max = 0 -------------
        // |score*log2e| <= 11.54 (rmsnorm bounds |q|,|k| = 8): no overflow.
        #pragma unroll
        for (int j = 0; j < 8; j++) {
            accS[j][0] = exp2f(accS[j][0]);
            accS[j][1] = exp2f(accS[j][1]);
            accS[j][2] = exp2f(accS[j][2]);
            accS[j][3] = exp2f(accS[j][3]);
            l0 += accS[j][0] + accS[j][1];
            l1 += accS[j][2] + accS[j][3];
        }

        // ---- O += P V (bf16x3, P register-resident as A fragments) ----
        #pragma unroll
        for (int kk = 0; kk < 4; kk++) {
            const float* p0 = accS[2 * kk];
            const float* p1 = accS[2 * kk + 1];
            uint32_t pah[4], pal[4];
            #pragma unroll
            for (int hseg = 0; hseg < 4; hseg++) {
                const float* ps = (hseg < 2) ? p0 : p1;
                float x = ps[(hseg & 1) * 2], y = ps[(hseg & 1) * 2 + 1];
                uint32_t hw = cvtpack(x, y);
                pah[hseg] = hw;
                float xh = __uint_as_float(hw << 16);
                float yh = __uint_as_float(hw & 0xffff0000u);
                pal[hseg] = cvtpack(x - xh, y - yh);
            }
            int kvb = kk * 16 + 2 * tig;
            #pragma unroll
            for (int j = 0; j < 8; j++) {
                const __nv_bfloat16* vr_h = sVth + (j * 8 + gid) * LDT + kvb;
                const __nv_bfloat16* vr_l = sVtl + (j * 8 + gid) * LDT + kvb;
                uint32_t vbh[2] = { lds32(vr_h), lds32(vr_h + 8) };
                uint32_t vbl[2] = { lds32(vr_l), lds32(vr_l + 8) };
                mma16816(accO[j], pah, vbh);
                mma16816(accO[j], pah, vbl);
                mma16816(accO[j], pal, vbh);
            }
        }
    }

    // ---- epilogue: one quad reduction of l, normalize, bf16 hi/lo ctx ----
    #pragma unroll
    for (int off = 1; off <= 2; off <<= 1) {
        l0 += __shfl_xor_sync(0xffffffff, l0, off);
        l1 += __shfl_xor_sync(0xffffffff, l1, off);
    }
    int b = bh >> 4, h = bh & 15;
    float i0 = 1.0f / l0, i1 = 1.0f / l1;
    int row0 = b * S + qt * BMA + w16 + gid;
    int row1 = row0 + 8;
    #pragma unroll
    for (int j = 0; j < 8; j++) {
        int col = h * HD + j * 8 + 2 * tig;
        float x0 = accO[j][0] * i0, x1 = accO[j][1] * i0;
        float x2 = accO[j][2] * i1, x3 = accO[j][3] * i1;
        __nv_bfloat16 a0 = __float2bfloat16_rn(x0), a1 = __float2bfloat16_rn(x1);
        __nv_bfloat16 a2 = __float2bfloat16_rn(x2), a3 = __float2bfloat16_rn(x3);
        size_t u0 = ((size_t)row0 * E + col) >> 1;
        size_t u1 = ((size_t)row1 * E + col) >> 1;
        reinterpret_cast<uint32_t*>(g_Ch)[u0] = packb(a0, a1);
        reinterpret_cast<uint32_t*>(g_Ch)[u1] = packb(a2, a3);
        reinterpret_cast<uint32_t*>(g_Cl)[u0] = packb(
            __float2bfloat16_rn(x0 - __bfloat162float(a0)),
            __float2bfloat16_rn(x1 - __bfloat162float(a1)));
        reinterpret_cast<uint32_t*>(g_Cl)[u1] = packb(
            __float2bfloat16_rn(x2 - __bfloat162float(a2)),
            __float2bfloat16_rn(x3 - __bfloat162float(a3)));
    }
}

// ---------------- kernel 4: projection (M=256, cp.async double-buffered) ----
// out[m][n] = sum_k ctx[m][k] * W[n][k] + bias[n]; tile 256x64, K-step 32.
// 2-stage smem pipeline: tile kt+1 streams in via cp.async while kt computes.
__global__ __launch_bounds__(256) void proj_kernel(
    const float* __restrict__ bias, float* __restrict__ out)
{
    extern __shared__ __nv_bfloat16 smp[];

    int tid = threadIdx.x, w = tid >> 5, t = tid & 31;
    int gid = t >> 2, tig = t & 3;
    int w16 = w * 16;
    int nb = blockIdx.x * 64, mb = blockIdx.y * 256;

    // per-stage pointers (elems): A hi | A lo | B hi | B lo
    auto stage_ptrs = [&](int st, __nv_bfloat16*& sAh, __nv_bfloat16*& sAl,
                          __nv_bfloat16*& sBh, __nv_bfloat16*& sBl) {
        __nv_bfloat16* b0 = smp + st * PROJ_STAGE_ELEMS;
        sAh = b0;
        sAl = b0 + 256 * LDP;
        sBh = b0 + 512 * LDP;
        sBl = b0 + 512 * LDP + 64 * LDP;
    };

    auto issue_tile = [&](int kt, int st) {
        __nv_bfloat16 *sAh, *sAl, *sBh, *sBl;
        stage_ptrs(st, sAh, sAl, sBh, sBl);
        #pragma unroll
        for (int i = 0; i < 4; i++) {
            int lin = i * 256 + tid;
            int r = lin >> 2, c = lin & 3;
            size_t g = (size_t)(mb + r) * E + kt * 32 + c * 8;
            cpasync16(sAh + r * LDP + c * 8, g_Ch + g);
            cpasync16(sAl + r * LDP + c * 8, g_Cl + g);
        }
        {
            int r = tid >> 2, c = tid & 3;
            size_t g = (size_t)(nb + r) * E + kt * 32 + c * 8;
            cpasync16(sBh + r * LDP + c * 8, g_Wh + g);
            cpasync16(sBl + r * LDP + c * 8, g_Wl + g);
        }
        CP_COMMIT();
    };

    float acc0[8][4], acc1[8][4];
    #pragma unroll
    for (int j = 0; j < 8; j++)
        #pragma unroll
        for (int c = 0; c < 4; c++) { acc0[j][c] = 0.f; acc1[j][c] = 0.f; }

    issue_tile(0, 0);

    for (int kt = 0; kt < E / 32; kt++) {
        CP_WAIT0();
        __syncthreads();
        if (kt + 1 < E / 32) issue_tile(kt + 1, (kt + 1) & 1);

        __nv_bfloat16 *sAh, *sAl, *sBh, *sBl;
        stage_ptrs(kt & 1, sAh, sAl, sBh, sBl);

        #pragma unroll
        for (int kk = 0; kk < 2; kk++) {
            int kb = kk * 16 + 2 * tig;
            const __nv_bfloat16* a0h = sAh + (w16 + gid) * LDP + kb;
            const __nv_bfloat16* a0l = sAl + (w16 + gid) * LDP + kb;
            const __nv_bfloat16* a1h = sAh + (128 + w16 + gid) * LDP + kb;
            const __nv_bfloat16* a1l = sAl + (128 + w16 + gid) * LDP + kb;
            uint32_t ah0[4], al0[4], ah1[4], al1[4];
            ah0[0] = lds32(a0h);               al0[0] = lds32(a0l);
            ah0[1] = lds32(a0h + 8 * LDP);     al0[1] = lds32(a0l + 8 * LDP);
            ah0[2] = lds32(a0h + 8);           al0[2] = lds32(a0l + 8);
            ah0[3] = lds32(a0h + 8 * LDP + 8); al0[3] = lds32(a0l + 8 * LDP + 8);
            ah1[0] = lds32(a1h);               al1[0] = lds32(a1l);
            ah1[1] = lds32(a1h + 8 * LDP);     al1[1] = lds32(a1l + 8 * LDP);
            ah1[2] = lds32(a1h + 8);           al1[2] = lds32(a1l + 8);
            ah1[3] = lds32(a1h + 8 * LDP + 8); al1[3] = lds32(a1l + 8 * LDP + 8);
            #pragma unroll
            for (int j = 0; j < 8; j++) {
                const __nv_bfloat16* br_h = sBh + (j * 8 + gid) * LDP + kb;
                const __nv_bfloat16* br_l = sBl + (j * 8 + gid) * LDP + kb;
                uint32_t bhf[2] = { lds32(br_h), lds32(br_h + 8) };
                uint32_t blf[2] = { lds32(br_l), lds32(br_l + 8) };
                mma16816(acc0[j], ah0, bhf);
                mma16816(acc0[j], ah0, blf);
                mma16816(acc0[j], al0, bhf);
                mma16816(acc1[j], ah1, bhf);
                mma16816(acc1[j], ah1, blf);
                mma16816(acc1[j], al1, bhf);
            }
        }
        __syncthreads();
    }

    int r0 = mb + w16 + gid;
    #pragma unroll
    for (int j = 0; j < 8; j++) {
        int c = nb + j * 8 + 2 * tig;
        float b0 = bias[c], b1 = bias[c + 1];
        *reinterpret_cast<float2*>(out + (size_t)r0 * E + c) =
            make_float2(acc0[j][0] + b0, acc0[j][1] + b1);
        *reinterpret_cast<float2*>(out + (size_t)(r0 + 8) * E + c) =
            make_float2(acc0[j][2] + b0, acc0[j][3] + b1);
        *reinterpret_cast<float2*>(out + (size_t)(r0 + 128) * E + c) =
            make_float2(acc1[j][0] + b0, acc1[j][1] + b1);
        *reinterpret_cast<float2*>(out + (size_t)(r0 + 136) * E + c) =
            make_float2(acc1[j][2] + b0, acc1[j][3] + b1);
    }
}

// ---------------------------------------------------------------------------
extern "C" void kernel_launch(void* const* d_in, const int* in_sizes, int n_in,
                              void* d_out, int out_size)
{
    const float* q    = (const float*)d_in[0];
    const float* k    = (const float*)d_in[1];
    const float* v    = (const float*)d_in[2];
    const float* qw   = (const float*)d_in[3];
    const float* kw   = (const float*)d_in[4];
    const float* W    = (const float*)d_in[5];
    const float* bias = (const float*)d_in[6];
    float* out = (float*)d_out;

    cudaFuncSetAttribute(attn_kernel,
                         cudaFuncAttributeMaxDynamicSharedMemorySize, SMEM_ATTN);
    cudaFuncSetAttribute(proj_kernel,
                         cudaFuncAttributeMaxDynamicSharedMemorySize, SMEM_PROJ);

    prep_kernel<<<(B * S * H) / 8, 256>>>(q, k, v, qw, kw);
    wconv_kernel<<<(E * E) / 256, 256>>>(W);
    attn_kernel<<<dim3(S / BMA, B * H), 256, SMEM_ATTN>>>();
    proj_kernel<<<dim3(E / 64, (B * S) / 256), 256, SMEM_PROJ>>>(bias, out);
}